// round 1
// baseline (speedup 1.0000x reference)
#include <cuda_runtime.h>
#include <math.h>
#include <float.h>

#define DEPTH  6
#define DIM    1024
#define HEADS  16
#define DH     64
#define INNER  2730
#define INNER2 5460
#define BATCH  2
#define SEQ    1024
#define TOK    (BATCH*SEQ)
#define NBUCK  32

// ---------------- scratch (device globals; no allocation allowed) ----------------
__device__ float g_x [TOK*DIM];
__device__ float g_h [TOK*DIM];
__device__ float g_q [TOK*DIM];
__device__ float g_kv[TOK*2*DH];
__device__ float g_o [TOK*DIM];
__device__ float g_g1[(size_t)TOK*INNER2];
__device__ float g_h2[(size_t)TOK*INNER];
__device__ float g_h3[(size_t)TOK*INNER];
__device__ float g_bias[SEQ*HEADS];

// ---------------- rel-pos bias precompute ----------------
__global__ void bias_kernel(const float* __restrict__ rel_emb){
    int idx = blockIdx.x*blockDim.x + threadIdx.x;   // delta*HEADS + h
    if (idx >= SEQ*HEADS) return;
    int delta = idx / HEADS;
    int h     = idx % HEADS;
    int bucket;
    if (delta < NBUCK/2) {
        bucket = delta;
    } else {
        float nf = (float)delta;
        int vl = (NBUCK/2) + (int)(logf(nf / (float)(NBUCK/2)) / logf(8.0f) * (float)(NBUCK/2));
        bucket = vl < (NBUCK-1) ? vl : (NBUCK-1);
    }
    g_bias[idx] = rel_emb[bucket*HEADS + h];
}

// ---------------- x scale copy (x*0.1 + x*0.9) ----------------
__global__ void scale_copy_kernel(const float* __restrict__ in, float* __restrict__ out, int n){
    int i = blockIdx.x*blockDim.x + threadIdx.x;
    if (i < n){ float v = in[i]; out[i] = v*0.1f + v*0.9f; }
}

// ---------------- LayerNorm (gain only) ----------------
__global__ __launch_bounds__(256) void ln_kernel(const float* __restrict__ in,
                                                 const float* __restrict__ g,
                                                 float* __restrict__ out, int D){
    int t = blockIdx.x;
    const float* row = in + (size_t)t*D;
    float s = 0.f, s2 = 0.f;
    for (int i = threadIdx.x; i < D; i += blockDim.x){ float v = row[i]; s += v; s2 += v*v; }
    __shared__ float sh1[8], sh2[8];
    int lane = threadIdx.x & 31, warp = threadIdx.x >> 5;
    #pragma unroll
    for (int off = 16; off; off >>= 1){
        s  += __shfl_xor_sync(0xffffffffu, s,  off);
        s2 += __shfl_xor_sync(0xffffffffu, s2, off);
    }
    if (lane == 0){ sh1[warp] = s; sh2[warp] = s2; }
    __syncthreads();
    if (warp == 0){
        s  = (lane < 8) ? sh1[lane] : 0.f;
        s2 = (lane < 8) ? sh2[lane] : 0.f;
        #pragma unroll
        for (int off = 4; off; off >>= 1){
            s  += __shfl_xor_sync(0xffffffffu, s,  off);
            s2 += __shfl_xor_sync(0xffffffffu, s2, off);
        }
        if (lane == 0){ sh1[0] = s; sh2[0] = s2; }
    }
    __syncthreads();
    float m   = sh1[0] / (float)D;
    float var = sh2[0] / (float)D - m*m;
    float r   = rsqrtf(var + 1e-5f);
    for (int i = threadIdx.x; i < D; i += blockDim.x)
        out[(size_t)t*D + i] = (row[i] - m) * r * g[i];
}

// ---------------- tiled SGEMM: C[M,N] = A[M,K] @ W[K,N] (+R) ----------------
__global__ __launch_bounds__(256) void gemm_kernel(const float* __restrict__ A,
                                                   const float* __restrict__ W,
                                                   const float* __restrict__ R,
                                                   float* __restrict__ C,
                                                   int M, int K, int N){
    __shared__ float As[16][68];
    __shared__ float Bs[16][68];
    int bm = blockIdx.y * 64;
    int bn = blockIdx.x * 64;
    int tx = threadIdx.x & 15;
    int ty = threadIdx.x >> 4;
    float acc[4][4] = {};
    int ar = threadIdx.x >> 2;            // 0..63
    int ak = (threadIdx.x & 3) * 4;       // 0,4,8,12
    int bk = threadIdx.x >> 4;            // 0..15
    int bc = (threadIdx.x & 15) * 4;      // 0..60
    for (int k0 = 0; k0 < K; k0 += 16){
        #pragma unroll
        for (int i = 0; i < 4; i++){
            int kg = k0 + ak + i;
            As[ak+i][ar] = (kg < K) ? A[(size_t)(bm+ar)*K + kg] : 0.f;
        }
        int kg = k0 + bk;
        #pragma unroll
        for (int i = 0; i < 4; i++){
            int cg = bn + bc + i;
            Bs[bk][bc+i] = (kg < K && cg < N) ? W[(size_t)kg*N + cg] : 0.f;
        }
        __syncthreads();
        #pragma unroll
        for (int k = 0; k < 16; k++){
            float a[4], b[4];
            #pragma unroll
            for (int i = 0; i < 4; i++) a[i] = As[k][ty*4+i];
            #pragma unroll
            for (int j = 0; j < 4; j++) b[j] = Bs[k][tx*4+j];
            #pragma unroll
            for (int i = 0; i < 4; i++)
                #pragma unroll
                for (int j = 0; j < 4; j++)
                    acc[i][j] += a[i] * b[j];
        }
        __syncthreads();
    }
    #pragma unroll
    for (int i = 0; i < 4; i++){
        int row = bm + ty*4 + i;
        #pragma unroll
        for (int j = 0; j < 4; j++){
            int col = bn + tx*4 + j;
            if (col < N){
                size_t idx = (size_t)row*N + col;
                float v = acc[i][j];
                if (R) v += R[idx];
                C[idx] = v;
            }
        }
    }
}

// ---------------- fused attention: per (b, h, 16-row tile) ----------------
#define AT_ROWS 16
#define ATTN_SMEM ((AT_ROWS*SEQ + AT_ROWS*DH + 2*64*65) * (int)sizeof(float))

__global__ __launch_bounds__(256) void attn_kernel(const float* __restrict__ q,
                                                   const float* __restrict__ kv,
                                                   float* __restrict__ o){
    extern __shared__ float sm[];
    float* S  = sm;                         // 16 x 1024 scores
    float* Qs = S  + AT_ROWS*SEQ;           // 16 x 64
    float* Ks = Qs + AT_ROWS*DH;            // 64 x 65
    float* Vs = Ks + 64*65;                 // 64 x 65
    int it = blockIdx.x;
    int h  = blockIdx.y;
    int b  = blockIdx.z;
    int i0 = it * AT_ROWS;
    int tid = threadIdx.x;

    for (int idx = tid; idx < AT_ROWS*DH; idx += 256){
        int r = idx / DH, d = idx % DH;
        Qs[r*DH + d] = q[(size_t)(b*SEQ + i0 + r)*DIM + h*DH + d] * 0.125f;
    }
    __syncthreads();

    int jmax = i0 + AT_ROWS - 1;
    int njt  = jmax/64 + 1;
    int jj = tid & 63;
    int rg = tid >> 6;                      // 0..3

    // ---- scores ----
    for (int jt = 0; jt < njt; jt++){
        for (int idx = tid; idx < 64*DH; idx += 256){
            int kr = idx / DH, d = idx % DH;
            Ks[kr*65 + d] = kv[(size_t)(b*SEQ + jt*64 + kr)*(2*DH) + d];
        }
        __syncthreads();
        int j = jt*64 + jj;
        #pragma unroll
        for (int ri = 0; ri < 4; ri++){
            int r = rg*4 + ri;
            float acc = 0.f;
            #pragma unroll
            for (int d = 0; d < DH; d++) acc += Qs[r*DH + d] * Ks[jj*65 + d];
            int i = i0 + r;
            S[r*SEQ + j] = (j <= i) ? (acc + g_bias[(i-j)*HEADS + h]) : -FLT_MAX;
        }
        __syncthreads();
    }

    // ---- softmax: 8 warps x 2 rows ----
    int warp = tid >> 5, lane = tid & 31;
    int ncol = njt * 64;
    for (int r = warp*2; r < warp*2 + 2; r++){
        int i = i0 + r;
        float mx = -FLT_MAX;
        for (int j = lane; j <= i; j += 32) mx = fmaxf(mx, S[r*SEQ + j]);
        #pragma unroll
        for (int off = 16; off; off >>= 1) mx = fmaxf(mx, __shfl_xor_sync(0xffffffffu, mx, off));
        float sum = 0.f;
        for (int j = lane; j <= i; j += 32) sum += expf(S[r*SEQ + j] - mx);
        #pragma unroll
        for (int off = 16; off; off >>= 1) sum += __shfl_xor_sync(0xffffffffu, sum, off);
        float inv = 1.f / sum;
        for (int j = lane; j < ncol; j += 32){
            float p = (j <= i) ? expf(S[r*SEQ + j] - mx) * inv : 0.f;
            S[r*SEQ + j] = p;
        }
    }
    __syncthreads();

    // ---- attn @ V ----
    int d = tid & 63;
    float accv[4] = {0.f, 0.f, 0.f, 0.f};
    for (int jt = 0; jt < njt; jt++){
        for (int idx = tid; idx < 64*DH; idx += 256){
            int vr = idx / DH, dd = idx % DH;
            Vs[vr*65 + dd] = kv[(size_t)(b*SEQ + jt*64 + vr)*(2*DH) + DH + dd];
        }
        __syncthreads();
        #pragma unroll
        for (int ri = 0; ri < 4; ri++){
            int r = rg*4 + ri;
            float a = 0.f;
            #pragma unroll 8
            for (int jl = 0; jl < 64; jl++) a += S[r*SEQ + jt*64 + jl] * Vs[jl*65 + d];
            accv[ri] += a;
        }
        __syncthreads();
    }
    #pragma unroll
    for (int ri = 0; ri < 4; ri++){
        int r = rg*4 + ri;
        o[(size_t)(b*SEQ + i0 + r)*DIM + h*DH + d] = accv[ri];
    }
}

// ---------------- fused causal conv(3) + GELU-GLU ----------------
__global__ __launch_bounds__(256) void convglu_kernel(const float* __restrict__ g1,
                                                      const float* __restrict__ cw,
                                                      float* __restrict__ out){
    int t = blockIdx.x;
    int n = t & (SEQ-1);
    size_t base = (size_t)t * INNER2;
    for (int c = threadIdx.x; c < INNER; c += blockDim.x){
        // channel c (a-path)
        float w0 = cw[c*3+0], w1 = cw[c*3+1], w2 = cw[c*3+2];
        float a = ((n >= 2) ? g1[base - 2*(size_t)INNER2 + c] : 0.f) * w0
                + ((n >= 1) ? g1[base -   (size_t)INNER2 + c] : 0.f) * w1
                +              g1[base + c] * w2;
        // channel c+INNER (gate path)
        int cg = c + INNER;
        float v0 = cw[cg*3+0], v1 = cw[cg*3+1], v2 = cw[cg*3+2];
        float g = ((n >= 2) ? g1[base - 2*(size_t)INNER2 + cg] : 0.f) * v0
                + ((n >= 1) ? g1[base -   (size_t)INNER2 + cg] : 0.f) * v1
                +              g1[base + cg] * v2;
        // exact gelu(gate) * a
        float gg = 0.5f * g * (1.f + erff(g * 0.70710678118654752f));
        out[(size_t)t*INNER + c] = gg * a;
    }
}

// ---------------- launch ----------------
static inline void run_gemm(const float* A, const float* W, const float* R, float* C,
                            int M, int K, int N){
    dim3 grid((N + 63)/64, M/64);
    gemm_kernel<<<grid, 256>>>(A, W, R, C, M, K, N);
}

extern "C" void kernel_launch(void* const* d_in, const int* in_sizes, int n_in,
                              void* d_out, int out_size){
    const float* x     = (const float*)d_in[0];
    const float* rel   = (const float*)d_in[1];
    const float* qn_g  = (const float*)d_in[2];
    const float* wq    = (const float*)d_in[3];
    const float* wkv   = (const float*)d_in[4];
    const float* wo    = (const float*)d_in[5];
    const float* ln1g  = (const float*)d_in[6];
    const float* w1    = (const float*)d_in[7];
    const float* convw = (const float*)d_in[8];
    const float* ln2g  = (const float*)d_in[9];
    const float* w2    = (const float*)d_in[10];
    const float* fing  = (const float*)d_in[11];
    float* out = (float*)d_out;

    float *px, *ph, *pq, *pkv, *po, *pg1, *ph2, *ph3;
    cudaGetSymbolAddress((void**)&px,  g_x);
    cudaGetSymbolAddress((void**)&ph,  g_h);
    cudaGetSymbolAddress((void**)&pq,  g_q);
    cudaGetSymbolAddress((void**)&pkv, g_kv);
    cudaGetSymbolAddress((void**)&po,  g_o);
    cudaGetSymbolAddress((void**)&pg1, g_g1);
    cudaGetSymbolAddress((void**)&ph2, g_h2);
    cudaGetSymbolAddress((void**)&ph3, g_h3);

    cudaFuncSetAttribute(attn_kernel, cudaFuncAttributeMaxDynamicSharedMemorySize, ATTN_SMEM);

    bias_kernel<<<(SEQ*HEADS + 255)/256, 256>>>(rel);
    scale_copy_kernel<<<(TOK*DIM + 255)/256, 256>>>(x, px, TOK*DIM);

    for (int l = 0; l < DEPTH; l++){
        // attention block
        ln_kernel<<<TOK, 256>>>(px, qn_g + l*DIM, ph, DIM);
        run_gemm(ph, wq  + (size_t)l*DIM*DIM,    nullptr, pq,  TOK, DIM, DIM);
        run_gemm(ph, wkv + (size_t)l*DIM*2*DH,   nullptr, pkv, TOK, DIM, 2*DH);
        dim3 agrid(SEQ/AT_ROWS, HEADS, BATCH);
        attn_kernel<<<agrid, 256, ATTN_SMEM>>>(pq, pkv, po);
        run_gemm(po, wo + (size_t)l*DIM*DIM, px, px, TOK, DIM, DIM);

        // conv-GLU MLP block
        ln_kernel<<<TOK, 256>>>(px, ln1g + l*DIM, ph, DIM);
        run_gemm(ph, w1 + (size_t)l*DIM*INNER2, nullptr, pg1, TOK, DIM, INNER2);
        convglu_kernel<<<TOK, 256>>>(pg1, convw + (size_t)l*INNER2*3, ph2);
        ln_kernel<<<TOK, 256>>>(ph2, ln2g + (size_t)l*INNER, ph3, INNER);
        run_gemm(ph3, w2 + (size_t)l*INNER*DIM, px, px, TOK, INNER, DIM);
    }
    ln_kernel<<<TOK, 256>>>(px, fing, out, DIM);
}

// round 2
// speedup vs baseline: 1.1057x; 1.1057x over previous
#include <cuda_runtime.h>
#include <math.h>
#include <float.h>

#define DEPTH  6
#define DIM    1024
#define HEADS  16
#define DH     64
#define INNER  2730
#define INNER_P 2732
#define INNER2 5460
#define BATCH  2
#define SEQ    1024
#define TOK    (BATCH*SEQ)
#define NBUCK  32

// ---------------- scratch (device globals; no allocation allowed) ----------------
__device__ float g_x [TOK*DIM];
__device__ float g_h [TOK*DIM];
__device__ float g_q [TOK*DIM];
__device__ float g_kv[TOK*2*DH];
__device__ float g_o [TOK*DIM];
__device__ float g_g1[(size_t)TOK*INNER2 + 16];
__device__ float g_h2[(size_t)TOK*INNER + 16];
__device__ float g_h3[(size_t)TOK*INNER_P + 16];
__device__ float g_bias[SEQ*HEADS];

// ---------------- rel-pos bias precompute ----------------
__global__ void bias_kernel(const float* __restrict__ rel_emb){
    int idx = blockIdx.x*blockDim.x + threadIdx.x;   // delta*HEADS + h
    if (idx >= SEQ*HEADS) return;
    int delta = idx / HEADS;
    int h     = idx % HEADS;
    int bucket;
    if (delta < NBUCK/2) {
        bucket = delta;
    } else {
        float nf = (float)delta;
        int vl = (NBUCK/2) + (int)(logf(nf / (float)(NBUCK/2)) / logf(8.0f) * (float)(NBUCK/2));
        bucket = vl < (NBUCK-1) ? vl : (NBUCK-1);
    }
    g_bias[idx] = rel_emb[bucket*HEADS + h];
}

// ---------------- x scale copy (x*0.1 + x*0.9) ----------------
__global__ void scale_copy_kernel(const float* __restrict__ in, float* __restrict__ out, int n){
    int i = blockIdx.x*blockDim.x + threadIdx.x;
    if (i < n){ float v = in[i]; out[i] = v*0.1f + v*0.9f; }
}

// ---------------- LayerNorm (gain only), out row stride ldo, pad zeroed ----------------
__global__ __launch_bounds__(256) void ln_kernel(const float* __restrict__ in,
                                                 const float* __restrict__ g,
                                                 float* __restrict__ out, int D, int ldo){
    int t = blockIdx.x;
    const float* row = in + (size_t)t*D;
    float s = 0.f, s2 = 0.f;
    for (int i = threadIdx.x; i < D; i += blockDim.x){ float v = row[i]; s += v; s2 += v*v; }
    __shared__ float sh1[8], sh2[8];
    int lane = threadIdx.x & 31, warp = threadIdx.x >> 5;
    #pragma unroll
    for (int off = 16; off; off >>= 1){
        s  += __shfl_xor_sync(0xffffffffu, s,  off);
        s2 += __shfl_xor_sync(0xffffffffu, s2, off);
    }
    if (lane == 0){ sh1[warp] = s; sh2[warp] = s2; }
    __syncthreads();
    if (warp == 0){
        s  = (lane < 8) ? sh1[lane] : 0.f;
        s2 = (lane < 8) ? sh2[lane] : 0.f;
        #pragma unroll
        for (int off = 4; off; off >>= 1){
            s  += __shfl_xor_sync(0xffffffffu, s,  off);
            s2 += __shfl_xor_sync(0xffffffffu, s2, off);
        }
        if (lane == 0){ sh1[0] = s; sh2[0] = s2; }
    }
    __syncthreads();
    float m   = sh1[0] / (float)D;
    float var = sh2[0] / (float)D - m*m;
    float r   = rsqrtf(var + 1e-5f);
    for (int i = threadIdx.x; i < D; i += blockDim.x)
        out[(size_t)t*ldo + i] = (row[i] - m) * r * g[i];
    for (int i = D + threadIdx.x; i < ldo; i += blockDim.x)
        out[(size_t)t*ldo + i] = 0.f;
}

// ---------------- 128x128x8 double-buffered SGEMM: C[M,N] = A[M,K]@W[K,N] (+R) ----------------
__global__ __launch_bounds__(256, 2) void gemm128_kernel(const float* __restrict__ A,
                                                         const float* __restrict__ W,
                                                         const float* __restrict__ R,
                                                         float* __restrict__ C,
                                                         int M, int K, int N, int lda){
    __shared__ float As[2][8][128];
    __shared__ float Bs[2][8][128];
    const int bm = blockIdx.y * 128;
    const int bn = blockIdx.x * 128;
    const int tid = threadIdx.x;
    const int tx = tid & 15, ty = tid >> 4;
    const int a_row = tid >> 1;              // 0..127
    const int a_cv  = (tid & 1) * 4;         // 0 or 4 (k offset)
    const int b_k   = tid >> 5;              // 0..7
    const int b_n   = (tid & 31) * 4;        // 0..124

    float acc[8][8] = {};
    const int ntiles = (K + 7) / 8;

    float4 av, bv;
    // prologue: tile 0
    {
        av = *reinterpret_cast<const float4*>(A + (size_t)(bm + a_row)*lda + a_cv);
        const float* avp = (const float*)&av;
        #pragma unroll
        for (int j = 0; j < 4; j++)
            As[0][a_cv + j][a_row] = (a_cv + j < K) ? avp[j] : 0.f;
        bool okb = (b_k < K) && (bn + b_n < N);
        bv = okb ? *reinterpret_cast<const float4*>(W + (size_t)b_k*N + bn + b_n)
                 : make_float4(0.f,0.f,0.f,0.f);
        *reinterpret_cast<float4*>(&Bs[0][b_k][b_n]) = bv;
    }
    __syncthreads();

    int buf = 0;
    for (int t = 0; t < ntiles; t++){
        const int k0n = (t + 1) * 8;
        const bool more = (t + 1 < ntiles);
        if (more){
            av = *reinterpret_cast<const float4*>(A + (size_t)(bm + a_row)*lda + k0n + a_cv);
            int kb = k0n + b_k;
            bool okb = (kb < K) && (bn + b_n < N);
            bv = okb ? *reinterpret_cast<const float4*>(W + (size_t)kb*N + bn + b_n)
                     : make_float4(0.f,0.f,0.f,0.f);
        }
        #pragma unroll
        for (int k = 0; k < 8; k++){
            float a[8], b[8];
            *(float4*)&a[0] = *(const float4*)&As[buf][k][ty*8];
            *(float4*)&a[4] = *(const float4*)&As[buf][k][ty*8 + 4];
            *(float4*)&b[0] = *(const float4*)&Bs[buf][k][tx*8];
            *(float4*)&b[4] = *(const float4*)&Bs[buf][k][tx*8 + 4];
            #pragma unroll
            for (int i = 0; i < 8; i++)
                #pragma unroll
                for (int j = 0; j < 8; j++)
                    acc[i][j] += a[i] * b[j];
        }
        if (more){
            int nb = buf ^ 1;
            const float* avp = (const float*)&av;
            #pragma unroll
            for (int j = 0; j < 4; j++)
                As[nb][a_cv + j][a_row] = (k0n + a_cv + j < K) ? avp[j] : 0.f;
            *reinterpret_cast<float4*>(&Bs[nb][b_k][b_n]) = bv;
        }
        __syncthreads();
        buf ^= 1;
    }

    #pragma unroll
    for (int i = 0; i < 8; i++){
        int row = bm + ty*8 + i;
        size_t base = (size_t)row * N;
        #pragma unroll
        for (int j = 0; j < 8; j++){
            int col = bn + tx*8 + j;
            if (col < N){
                float v = acc[i][j];
                if (R) v += R[base + col];
                C[base + col] = v;
            }
        }
    }
}

// ---------------- small SGEMM (64x64x16) for skinny N (wkv) ----------------
__global__ __launch_bounds__(256) void gemm64_kernel(const float* __restrict__ A,
                                                     const float* __restrict__ W,
                                                     const float* __restrict__ R,
                                                     float* __restrict__ C,
                                                     int M, int K, int N){
    __shared__ float As[16][68];
    __shared__ float Bs[16][68];
    int bm = blockIdx.y * 64;
    int bn = blockIdx.x * 64;
    int tx = threadIdx.x & 15;
    int ty = threadIdx.x >> 4;
    float acc[4][4] = {};
    int ar = threadIdx.x >> 2;
    int ak = (threadIdx.x & 3) * 4;
    int bk = threadIdx.x >> 4;
    int bc = (threadIdx.x & 15) * 4;
    for (int k0 = 0; k0 < K; k0 += 16){
        #pragma unroll
        for (int i = 0; i < 4; i++){
            int kg = k0 + ak + i;
            As[ak+i][ar] = (kg < K) ? A[(size_t)(bm+ar)*K + kg] : 0.f;
        }
        int kg = k0 + bk;
        #pragma unroll
        for (int i = 0; i < 4; i++){
            int cg = bn + bc + i;
            Bs[bk][bc+i] = (kg < K && cg < N) ? W[(size_t)kg*N + cg] : 0.f;
        }
        __syncthreads();
        #pragma unroll
        for (int k = 0; k < 16; k++){
            float a[4], b[4];
            #pragma unroll
            for (int i = 0; i < 4; i++) a[i] = As[k][ty*4+i];
            #pragma unroll
            for (int j = 0; j < 4; j++) b[j] = Bs[k][tx*4+j];
            #pragma unroll
            for (int i = 0; i < 4; i++)
                #pragma unroll
                for (int j = 0; j < 4; j++)
                    acc[i][j] += a[i] * b[j];
        }
        __syncthreads();
    }
    #pragma unroll
    for (int i = 0; i < 4; i++){
        int row = bm + ty*4 + i;
        #pragma unroll
        for (int j = 0; j < 4; j++){
            int col = bn + tx*4 + j;
            if (col < N){
                size_t idx = (size_t)row*N + col;
                float v = acc[i][j];
                if (R) v += R[idx];
                C[idx] = v;
            }
        }
    }
}

// ---------------- fused attention: per (b, h, 16-row tile) ----------------
#define AT_ROWS 16
#define ATTN_SMEM ((AT_ROWS*SEQ + AT_ROWS*DH + 2*64*65) * (int)sizeof(float))

__global__ __launch_bounds__(256) void attn_kernel(const float* __restrict__ q,
                                                   const float* __restrict__ kv,
                                                   float* __restrict__ o){
    extern __shared__ float sm[];
    float* S  = sm;                         // 16 x 1024 scores
    float* Qs = S  + AT_ROWS*SEQ;           // 16 x 64
    float* Ks = Qs + AT_ROWS*DH;            // 64 x 65
    float* Vs = Ks + 64*65;                 // 64 x 65
    int it = blockIdx.x;
    int h  = blockIdx.y;
    int b  = blockIdx.z;
    int i0 = it * AT_ROWS;
    int tid = threadIdx.x;

    for (int idx = tid; idx < AT_ROWS*DH; idx += 256){
        int r = idx / DH, d = idx % DH;
        Qs[r*DH + d] = q[(size_t)(b*SEQ + i0 + r)*DIM + h*DH + d] * 0.125f;
    }
    __syncthreads();

    int jmax = i0 + AT_ROWS - 1;
    int njt  = jmax/64 + 1;
    int jj = tid & 63;
    int rg = tid >> 6;                      // 0..3

    // ---- scores ----
    for (int jt = 0; jt < njt; jt++){
        for (int idx = tid; idx < 64*DH; idx += 256){
            int kr = idx / DH, d = idx % DH;
            Ks[kr*65 + d] = kv[(size_t)(b*SEQ + jt*64 + kr)*(2*DH) + d];
        }
        __syncthreads();
        int j = jt*64 + jj;
        #pragma unroll
        for (int ri = 0; ri < 4; ri++){
            int r = rg*4 + ri;
            float acc = 0.f;
            #pragma unroll
            for (int d = 0; d < DH; d++) acc += Qs[r*DH + d] * Ks[jj*65 + d];
            int i = i0 + r;
            S[r*SEQ + j] = (j <= i) ? (acc + g_bias[(i-j)*HEADS + h]) : -FLT_MAX;
        }
        __syncthreads();
    }

    // ---- softmax: 8 warps x 2 rows ----
    int warp = tid >> 5, lane = tid & 31;
    int ncol = njt * 64;
    for (int r = warp*2; r < warp*2 + 2; r++){
        int i = i0 + r;
        float mx = -FLT_MAX;
        for (int j = lane; j <= i; j += 32) mx = fmaxf(mx, S[r*SEQ + j]);
        #pragma unroll
        for (int off = 16; off; off >>= 1) mx = fmaxf(mx, __shfl_xor_sync(0xffffffffu, mx, off));
        float sum = 0.f;
        for (int j = lane; j <= i; j += 32) sum += expf(S[r*SEQ + j] - mx);
        #pragma unroll
        for (int off = 16; off; off >>= 1) sum += __shfl_xor_sync(0xffffffffu, sum, off);
        float inv = 1.f / sum;
        for (int j = lane; j < ncol; j += 32){
            float p = (j <= i) ? expf(S[r*SEQ + j] - mx) * inv : 0.f;
            S[r*SEQ + j] = p;
        }
    }
    __syncthreads();

    // ---- attn @ V ----
    int d = tid & 63;
    float accv[4] = {0.f, 0.f, 0.f, 0.f};
    for (int jt = 0; jt < njt; jt++){
        for (int idx = tid; idx < 64*DH; idx += 256){
            int vr = idx / DH, dd = idx % DH;
            Vs[vr*65 + dd] = kv[(size_t)(b*SEQ + jt*64 + vr)*(2*DH) + DH + dd];
        }
        __syncthreads();
        #pragma unroll
        for (int ri = 0; ri < 4; ri++){
            int r = rg*4 + ri;
            float a = 0.f;
            #pragma unroll 8
            for (int jl = 0; jl < 64; jl++) a += S[r*SEQ + jt*64 + jl] * Vs[jl*65 + d];
            accv[ri] += a;
        }
        __syncthreads();
    }
    #pragma unroll
    for (int ri = 0; ri < 4; ri++){
        int r = rg*4 + ri;
        o[(size_t)(b*SEQ + i0 + r)*DIM + h*DH + d] = accv[ri];
    }
}

// ---------------- fused causal conv(3) + GELU-GLU ----------------
__global__ __launch_bounds__(256) void convglu_kernel(const float* __restrict__ g1,
                                                      const float* __restrict__ cw,
                                                      float* __restrict__ out){
    int t = blockIdx.x;
    int n = t & (SEQ-1);
    size_t base = (size_t)t * INNER2;
    for (int c = threadIdx.x; c < INNER; c += blockDim.x){
        float w0 = cw[c*3+0], w1 = cw[c*3+1], w2 = cw[c*3+2];
        float a = ((n >= 2) ? g1[base - 2*(size_t)INNER2 + c] : 0.f) * w0
                + ((n >= 1) ? g1[base -   (size_t)INNER2 + c] : 0.f) * w1
                +              g1[base + c] * w2;
        int cg = c + INNER;
        float v0 = cw[cg*3+0], v1 = cw[cg*3+1], v2 = cw[cg*3+2];
        float g = ((n >= 2) ? g1[base - 2*(size_t)INNER2 + cg] : 0.f) * v0
                + ((n >= 1) ? g1[base -   (size_t)INNER2 + cg] : 0.f) * v1
                +              g1[base + cg] * v2;
        float gg = 0.5f * g * (1.f + erff(g * 0.70710678118654752f));
        out[(size_t)t*INNER + c] = gg * a;
    }
}

// ---------------- launch helpers ----------------
static inline void run_gemm128(const float* A, const float* W, const float* R, float* C,
                               int M, int K, int N, int lda){
    dim3 grid((N + 127)/128, M/128);
    gemm128_kernel<<<grid, 256>>>(A, W, R, C, M, K, N, lda);
}

extern "C" void kernel_launch(void* const* d_in, const int* in_sizes, int n_in,
                              void* d_out, int out_size){
    const float* x     = (const float*)d_in[0];
    const float* rel   = (const float*)d_in[1];
    const float* qn_g  = (const float*)d_in[2];
    const float* wq    = (const float*)d_in[3];
    const float* wkv   = (const float*)d_in[4];
    const float* wo    = (const float*)d_in[5];
    const float* ln1g  = (const float*)d_in[6];
    const float* w1    = (const float*)d_in[7];
    const float* convw = (const float*)d_in[8];
    const float* ln2g  = (const float*)d_in[9];
    const float* w2    = (const float*)d_in[10];
    const float* fing  = (const float*)d_in[11];
    float* out = (float*)d_out;

    float *px, *ph, *pq, *pkv, *po, *pg1, *ph2, *ph3;
    cudaGetSymbolAddress((void**)&px,  g_x);
    cudaGetSymbolAddress((void**)&ph,  g_h);
    cudaGetSymbolAddress((void**)&pq,  g_q);
    cudaGetSymbolAddress((void**)&pkv, g_kv);
    cudaGetSymbolAddress((void**)&po,  g_o);
    cudaGetSymbolAddress((void**)&pg1, g_g1);
    cudaGetSymbolAddress((void**)&ph2, g_h2);
    cudaGetSymbolAddress((void**)&ph3, g_h3);

    cudaFuncSetAttribute(attn_kernel, cudaFuncAttributeMaxDynamicSharedMemorySize, ATTN_SMEM);

    bias_kernel<<<(SEQ*HEADS + 255)/256, 256>>>(rel);
    scale_copy_kernel<<<(TOK*DIM + 255)/256, 256>>>(x, px, TOK*DIM);

    for (int l = 0; l < DEPTH; l++){
        // attention block
        ln_kernel<<<TOK, 256>>>(px, qn_g + l*DIM, ph, DIM, DIM);
        run_gemm128(ph, wq + (size_t)l*DIM*DIM, nullptr, pq, TOK, DIM, DIM, DIM);
        {
            dim3 grid((2*DH + 63)/64, TOK/64);
            gemm64_kernel<<<grid, 256>>>(ph, wkv + (size_t)l*DIM*2*DH, nullptr, pkv, TOK, DIM, 2*DH);
        }
        dim3 agrid(SEQ/AT_ROWS, HEADS, BATCH);
        attn_kernel<<<agrid, 256, ATTN_SMEM>>>(pq, pkv, po);
        run_gemm128(po, wo + (size_t)l*DIM*DIM, px, px, TOK, DIM, DIM, DIM);

        // conv-GLU MLP block
        ln_kernel<<<TOK, 256>>>(px, ln1g + l*DIM, ph, DIM, DIM);
        run_gemm128(ph, w1 + (size_t)l*DIM*INNER2, nullptr, pg1, TOK, DIM, INNER2, DIM);
        convglu_kernel<<<TOK, 256>>>(pg1, convw + (size_t)l*INNER2*3, ph2);
        ln_kernel<<<TOK, 256>>>(ph2, ln2g + (size_t)l*INNER, ph3, INNER, INNER_P);
        run_gemm128(ph3, w2 + (size_t)l*INNER*DIM, px, px, TOK, INNER, DIM, INNER_P);
    }
    ln_kernel<<<TOK, 256>>>(px, fing, out, DIM, DIM);
}

// round 5
// speedup vs baseline: 1.5337x; 1.3871x over previous
#include <cuda_runtime.h>
#include <math.h>
#include <float.h>
#include <stdint.h>

#define DEPTH  6
#define DIM    1024
#define HEADS  16
#define DH     64
#define INNER  2730
#define INNER_P 2732
#define INNER2 5460
#define BATCH  2
#define SEQ    1024
#define TOK    (BATCH*SEQ)
#define NBUCK  32

// ---------------- scratch (device globals; no allocation allowed) ----------------
__device__ float g_x [TOK*DIM];
__device__ float g_h [TOK*DIM];
__device__ float g_q [TOK*DIM];
__device__ float g_kv[TOK*2*DH];
__device__ float g_o [TOK*DIM];
__device__ float g_g1[(size_t)TOK*INNER2 + 32];
__device__ float g_h2[(size_t)TOK*INNER + 32];
__device__ float g_h3[(size_t)TOK*INNER_P + 32];
__device__ float g_bias[SEQ*HEADS];

// ---------------- rel-pos bias precompute ----------------
__global__ void bias_kernel(const float* __restrict__ rel_emb){
    int idx = blockIdx.x*blockDim.x + threadIdx.x;
    if (idx >= SEQ*HEADS) return;
    int delta = idx / HEADS;
    int h     = idx % HEADS;
    int bucket;
    if (delta < NBUCK/2) {
        bucket = delta;
    } else {
        float nf = (float)delta;
        int vl = (NBUCK/2) + (int)(logf(nf / (float)(NBUCK/2)) / logf(8.0f) * (float)(NBUCK/2));
        bucket = vl < (NBUCK-1) ? vl : (NBUCK-1);
    }
    g_bias[idx] = rel_emb[bucket*HEADS + h];
}

__global__ void scale_copy_kernel(const float* __restrict__ in, float* __restrict__ out, int n){
    int i = blockIdx.x*blockDim.x + threadIdx.x;
    if (i < n){ float v = in[i]; out[i] = v*0.1f + v*0.9f; }
}

// ---------------- LayerNorm (gain only), out row stride ldo, pad zeroed ----------------
__global__ __launch_bounds__(256) void ln_kernel(const float* __restrict__ in,
                                                 const float* __restrict__ g,
                                                 float* __restrict__ out, int D, int ldo){
    int t = blockIdx.x;
    const float* row = in + (size_t)t*D;
    float s = 0.f, s2 = 0.f;
    for (int i = threadIdx.x; i < D; i += blockDim.x){ float v = row[i]; s += v; s2 += v*v; }
    __shared__ float sh1[8], sh2[8];
    int lane = threadIdx.x & 31, warp = threadIdx.x >> 5;
    #pragma unroll
    for (int off = 16; off; off >>= 1){
        s  += __shfl_xor_sync(0xffffffffu, s,  off);
        s2 += __shfl_xor_sync(0xffffffffu, s2, off);
    }
    if (lane == 0){ sh1[warp] = s; sh2[warp] = s2; }
    __syncthreads();
    if (warp == 0){
        s  = (lane < 8) ? sh1[lane] : 0.f;
        s2 = (lane < 8) ? sh2[lane] : 0.f;
        #pragma unroll
        for (int off = 4; off; off >>= 1){
            s  += __shfl_xor_sync(0xffffffffu, s,  off);
            s2 += __shfl_xor_sync(0xffffffffu, s2, off);
        }
        if (lane == 0){ sh1[0] = s; sh2[0] = s2; }
    }
    __syncthreads();
    float m   = sh1[0] / (float)D;
    float var = sh2[0] / (float)D - m*m;
    float r   = rsqrtf(var + 1e-5f);
    for (int i = threadIdx.x; i < D; i += blockDim.x)
        out[(size_t)t*ldo + i] = (row[i] - m) * r * g[i];
    for (int i = D + threadIdx.x; i < ldo; i += blockDim.x)
        out[(size_t)t*ldo + i] = 0.f;
}

// ---------------- tf32 helpers ----------------
__device__ __forceinline__ float to_tf32(float x){
    uint32_t u; asm("cvt.rna.tf32.f32 %0, %1;" : "=r"(u) : "f"(x));
    return __uint_as_float(u);
}
__device__ __forceinline__ void mma_tf32(float* d, const uint32_t* a, const uint32_t* b){
    asm volatile(
        "mma.sync.aligned.m16n8k8.row.col.f32.tf32.tf32.f32 "
        "{%0,%1,%2,%3}, {%4,%5,%6,%7}, {%8,%9}, {%0,%1,%2,%3};\n"
        : "+f"(d[0]), "+f"(d[1]), "+f"(d[2]), "+f"(d[3])
        : "r"(a[0]), "r"(a[1]), "r"(a[2]), "r"(a[3]), "r"(b[0]), "r"(b[1]));
}

// ---------------- tf32 MMA GEMM: C[M,N] = A[M,K]@W[K,N] (+R) ----------------
// Block 128x128, KT=16, double-buffered, fragment-permuted smem.
// A rows must be readable up to lda-rounded K+16 (pads provided); B guarded.
__global__ __launch_bounds__(256, 2) void gemm_mma_kernel(const float* __restrict__ A,
                                                          const float* __restrict__ W,
                                                          const float* __restrict__ R,
                                                          float* __restrict__ C,
                                                          int M, int K, int N, int lda){
    // A_s: [g(2)*8+mt(8)][lane(32)][j(4)]   -> 2048 floats
    // B_s: [g(2)*16+nt(16)][lane(32)][j(2)] -> 2048 floats
    __shared__ float As[2][2048];
    __shared__ float Bs[2][2048];

    const int bm = blockIdx.y * 128;
    const int bn = blockIdx.x * 128;
    const int t  = threadIdx.x;
    const int lane = t & 31;
    const int warp = t >> 5;
    const int wm = warp >> 2;          // 0..1  (64 rows each)
    const int wn = warp & 3;           // 0..3  (32 cols each)

    // staging indices
    const int ar = t >> 1;             // 0..127 A row
    const int acb = (t & 1) * 8;       // A col base (0 or 8)
    const int bkr = t >> 4;            // 0..15  B k-row
    const int bcb = (t & 15) * 8;      // B col base

    const int ntiles = (K + 15) / 16;
    float acc[4][4][4];
    #pragma unroll
    for (int i = 0; i < 4; i++)
        #pragma unroll
        for (int j = 0; j < 4; j++)
            #pragma unroll
            for (int q = 0; q < 4; q++) acc[i][j][q] = 0.f;

    float a_vals[8], b_vals[8];

    // ---- load gmem tile (k0) into regs ----
    auto load_tile = [&](int k0){
        const float* Ap = A + (size_t)(bm + ar)*lda + k0 + acb;
        float4 v0 = *reinterpret_cast<const float4*>(Ap);
        float4 v1 = *reinterpret_cast<const float4*>(Ap + 4);
        a_vals[0]=v0.x; a_vals[1]=v0.y; a_vals[2]=v0.z; a_vals[3]=v0.w;
        a_vals[4]=v1.x; a_vals[5]=v1.y; a_vals[6]=v1.z; a_vals[7]=v1.w;
        int kg = k0 + bkr;
        if (kg < K && bn + bcb + 7 < N){
            const float* Bp = W + (size_t)kg*N + bn + bcb;
            float4 w0 = *reinterpret_cast<const float4*>(Bp);
            float4 w1 = *reinterpret_cast<const float4*>(Bp + 4);
            b_vals[0]=w0.x; b_vals[1]=w0.y; b_vals[2]=w0.z; b_vals[3]=w0.w;
            b_vals[4]=w1.x; b_vals[5]=w1.y; b_vals[6]=w1.z; b_vals[7]=w1.w;
        } else {
            #pragma unroll
            for (int e = 0; e < 8; e++){
                int col = bn + bcb + e;
                b_vals[e] = (kg < K && col < N) ? W[(size_t)kg*N + col] : 0.f;
            }
        }
    };
    // ---- scatter regs into permuted smem ----
    auto store_tile = [&](int buf){
        const int mt = ar >> 4, rr = ar & 15;
        const int jbit0 = rr >> 3;          // +8 row bit
        const int alane_base = (rr & 7) * 4;
        #pragma unroll
        for (int e = 0; e < 8; e++){
            int kk = acb + e;
            int g = kk >> 3;
            int al = alane_base + (kk & 3);
            int j = ((kk >> 2) & 1) * 2 + jbit0;
            As[buf][((g*8 + mt)*32 + al)*4 + j] = to_tf32(a_vals[e]);
        }
        const int jb = (bkr >> 2) & 1;
        const int g2 = bkr >> 3;
        const int klow = bkr & 3;
        #pragma unroll
        for (int e = 0; e < 8; e++){
            int n = bcb + e;
            int nt = n >> 3, nr = n & 7;
            Bs[buf][((g2*16 + nt)*32 + nr*4 + klow)*2 + jb] = to_tf32(b_vals[e]);
        }
    };

    load_tile(0);
    store_tile(0);
    __syncthreads();

    int buf = 0;
    for (int tile = 0; tile < ntiles; tile++){
        const bool more = (tile + 1 < ntiles);
        if (more) load_tile((tile + 1) * 16);

        #pragma unroll
        for (int g = 0; g < 2; g++){
            uint32_t afr[4][4], bfr[4][2];
            #pragma unroll
            for (int i = 0; i < 4; i++)
                *reinterpret_cast<float4*>(afr[i]) =
                    *reinterpret_cast<const float4*>(&As[buf][((g*8 + wm*4 + i)*32 + lane)*4]);
            #pragma unroll
            for (int jn = 0; jn < 4; jn++)
                *reinterpret_cast<float2*>(bfr[jn]) =
                    *reinterpret_cast<const float2*>(&Bs[buf][((g*16 + wn*4 + jn)*32 + lane)*2]);
            #pragma unroll
            for (int i = 0; i < 4; i++)
                #pragma unroll
                for (int jn = 0; jn < 4; jn++)
                    mma_tf32(acc[i][jn], afr[i], bfr[jn]);
        }

        if (more){
            store_tile(buf ^ 1);
        }
        __syncthreads();
        buf ^= 1;
    }

    // ---- epilogue ----
    const int r0 = bm + wm*64 + (lane >> 2);
    const int c0 = bn + wn*32 + (lane & 3)*2;
    #pragma unroll
    for (int i = 0; i < 4; i++){
        #pragma unroll
        for (int jn = 0; jn < 4; jn++){
            int col = c0 + jn*8;
            #pragma unroll
            for (int half = 0; half < 2; half++){
                int row = r0 + i*16 + half*8;
                size_t base = (size_t)row * N;
                float v0 = acc[i][jn][half*2 + 0];
                float v1 = acc[i][jn][half*2 + 1];
                if (col + 1 < N){
                    if (R){ v0 += R[base + col]; v1 += R[base + col + 1]; }
                    C[base + col]     = v0;
                    C[base + col + 1] = v1;
                } else if (col < N){
                    if (R) v0 += R[base + col];
                    C[base + col] = v0;
                }
            }
        }
    }
}

// ---------------- fused attention: per (b, h, 16-row tile) ----------------
#define AT_ROWS 16
#define ATTN_SMEM ((AT_ROWS*SEQ + AT_ROWS*DH + 2*64*65) * (int)sizeof(float))

__global__ __launch_bounds__(256) void attn_kernel(const float* __restrict__ q,
                                                   const float* __restrict__ kv,
                                                   float* __restrict__ o){
    extern __shared__ float sm[];
    float* S  = sm;
    float* Qs = S  + AT_ROWS*SEQ;
    float* Ks = Qs + AT_ROWS*DH;
    float* Vs = Ks + 64*65;
    int it = blockIdx.x;
    int h  = blockIdx.y;
    int b  = blockIdx.z;
    int i0 = it * AT_ROWS;
    int tid = threadIdx.x;

    for (int idx = tid; idx < AT_ROWS*DH; idx += 256){
        int r = idx / DH, d = idx % DH;
        Qs[r*DH + d] = q[(size_t)(b*SEQ + i0 + r)*DIM + h*DH + d] * 0.125f;
    }
    __syncthreads();

    int jmax = i0 + AT_ROWS - 1;
    int njt  = jmax/64 + 1;
    int jj = tid & 63;
    int rg = tid >> 6;

    for (int jt = 0; jt < njt; jt++){
        for (int idx = tid; idx < 64*DH; idx += 256){
            int kr = idx / DH, d = idx % DH;
            Ks[kr*65 + d] = kv[(size_t)(b*SEQ + jt*64 + kr)*(2*DH) + d];
        }
        __syncthreads();
        int j = jt*64 + jj;
        #pragma unroll
        for (int ri = 0; ri < 4; ri++){
            int r = rg*4 + ri;
            float acc = 0.f;
            #pragma unroll
            for (int d = 0; d < DH; d++) acc += Qs[r*DH + d] * Ks[jj*65 + d];
            int i = i0 + r;
            S[r*SEQ + j] = (j <= i) ? (acc + g_bias[(i-j)*HEADS + h]) : -FLT_MAX;
        }
        __syncthreads();
    }

    int warp = tid >> 5, lane = tid & 31;
    int ncol = njt * 64;
    for (int r = warp*2; r < warp*2 + 2; r++){
        int i = i0 + r;
        float mx = -FLT_MAX;
        for (int j = lane; j <= i; j += 32) mx = fmaxf(mx, S[r*SEQ + j]);
        #pragma unroll
        for (int off = 16; off; off >>= 1) mx = fmaxf(mx, __shfl_xor_sync(0xffffffffu, mx, off));
        float sum = 0.f;
        for (int j = lane; j <= i; j += 32) sum += expf(S[r*SEQ + j] - mx);
        #pragma unroll
        for (int off = 16; off; off >>= 1) sum += __shfl_xor_sync(0xffffffffu, sum, off);
        float inv = 1.f / sum;
        for (int j = lane; j < ncol; j += 32){
            float p = (j <= i) ? expf(S[r*SEQ + j] - mx) * inv : 0.f;
            S[r*SEQ + j] = p;
        }
    }
    __syncthreads();

    int d = tid & 63;
    float accv[4] = {0.f, 0.f, 0.f, 0.f};
    for (int jt = 0; jt < njt; jt++){
        for (int idx = tid; idx < 64*DH; idx += 256){
            int vr = idx / DH, dd = idx % DH;
            Vs[vr*65 + dd] = kv[(size_t)(b*SEQ + jt*64 + vr)*(2*DH) + DH + dd];
        }
        __syncthreads();
        #pragma unroll
        for (int ri = 0; ri < 4; ri++){
            int r = rg*4 + ri;
            float a = 0.f;
            #pragma unroll 8
            for (int jl = 0; jl < 64; jl++) a += S[r*SEQ + jt*64 + jl] * Vs[jl*65 + d];
            accv[ri] += a;
        }
        __syncthreads();
    }
    #pragma unroll
    for (int ri = 0; ri < 4; ri++){
        int r = rg*4 + ri;
        o[(size_t)(b*SEQ + i0 + r)*DIM + h*DH + d] = accv[ri];
    }
}

// ---------------- fused causal conv(3) + GELU-GLU ----------------
__global__ __launch_bounds__(256) void convglu_kernel(const float* __restrict__ g1,
                                                      const float* __restrict__ cw,
                                                      float* __restrict__ out){
    int t = blockIdx.x;
    int n = t & (SEQ-1);
    size_t base = (size_t)t * INNER2;
    for (int c = threadIdx.x; c < INNER; c += blockDim.x){
        float w0 = cw[c*3+0], w1 = cw[c*3+1], w2 = cw[c*3+2];
        float a = ((n >= 2) ? g1[base - 2*(size_t)INNER2 + c] : 0.f) * w0
                + ((n >= 1) ? g1[base -   (size_t)INNER2 + c] : 0.f) * w1
                +              g1[base + c] * w2;
        int cg = c + INNER;
        float v0 = cw[cg*3+0], v1 = cw[cg*3+1], v2 = cw[cg*3+2];
        float g = ((n >= 2) ? g1[base - 2*(size_t)INNER2 + cg] : 0.f) * v0
                + ((n >= 1) ? g1[base -   (size_t)INNER2 + cg] : 0.f) * v1
                +              g1[base + cg] * v2;
        float gg = 0.5f * g * (1.f + erff(g * 0.70710678118654752f));
        out[(size_t)t*INNER + c] = gg * a;
    }
}

// ---------------- launch helpers ----------------
static inline void run_gemm(const float* A, const float* W, const float* R, float* C,
                            int M, int K, int N, int lda){
    dim3 grid((N + 127)/128, M/128);
    gemm_mma_kernel<<<grid, 256>>>(A, W, R, C, M, K, N, lda);
}

extern "C" void kernel_launch(void* const* d_in, const int* in_sizes, int n_in,
                              void* d_out, int out_size){
    const float* x     = (const float*)d_in[0];
    const float* rel   = (const float*)d_in[1];
    const float* qn_g  = (const float*)d_in[2];
    const float* wq    = (const float*)d_in[3];
    const float* wkv   = (const float*)d_in[4];
    const float* wo    = (const float*)d_in[5];
    const float* ln1g  = (const float*)d_in[6];
    const float* w1    = (const float*)d_in[7];
    const float* convw = (const float*)d_in[8];
    const float* ln2g  = (const float*)d_in[9];
    const float* w2    = (const float*)d_in[10];
    const float* fing  = (const float*)d_in[11];
    float* out = (float*)d_out;

    float *px, *ph, *pq, *pkv, *po, *pg1, *ph2, *ph3;
    cudaGetSymbolAddress((void**)&px,  g_x);
    cudaGetSymbolAddress((void**)&ph,  g_h);
    cudaGetSymbolAddress((void**)&pq,  g_q);
    cudaGetSymbolAddress((void**)&pkv, g_kv);
    cudaGetSymbolAddress((void**)&po,  g_o);
    cudaGetSymbolAddress((void**)&pg1, g_g1);
    cudaGetSymbolAddress((void**)&ph2, g_h2);
    cudaGetSymbolAddress((void**)&ph3, g_h3);

    cudaFuncSetAttribute(attn_kernel, cudaFuncAttributeMaxDynamicSharedMemorySize, ATTN_SMEM);

    bias_kernel<<<(SEQ*HEADS + 255)/256, 256>>>(rel);
    scale_copy_kernel<<<(TOK*DIM + 255)/256, 256>>>(x, px, TOK*DIM);

    for (int l = 0; l < DEPTH; l++){
        // attention block
        ln_kernel<<<TOK, 256>>>(px, qn_g + l*DIM, ph, DIM, DIM);
        run_gemm(ph, wq  + (size_t)l*DIM*DIM,  nullptr, pq,  TOK, DIM, DIM,  DIM);
        run_gemm(ph, wkv + (size_t)l*DIM*2*DH, nullptr, pkv, TOK, DIM, 2*DH, DIM);
        dim3 agrid(SEQ/AT_ROWS, HEADS, BATCH);
        attn_kernel<<<agrid, 256, ATTN_SMEM>>>(pq, pkv, po);
        run_gemm(po, wo + (size_t)l*DIM*DIM, px, px, TOK, DIM, DIM, DIM);

        // conv-GLU MLP block
        ln_kernel<<<TOK, 256>>>(px, ln1g + l*DIM, ph, DIM, DIM);
        run_gemm(ph, w1 + (size_t)l*DIM*INNER2, nullptr, pg1, TOK, DIM, INNER2, DIM);
        convglu_kernel<<<TOK, 256>>>(pg1, convw + (size_t)l*INNER2*3, ph2);
        ln_kernel<<<TOK, 256>>>(ph2, ln2g + (size_t)l*INNER, ph3, INNER, INNER_P);
        run_gemm(ph3, w2 + (size_t)l*INNER*DIM, px, px, TOK, INNER, DIM, INNER_P);
    }
    ln_kernel<<<TOK, 256>>>(px, fing, out, DIM, DIM);
}

// round 6
// speedup vs baseline: 1.8250x; 1.1899x over previous
#include <cuda_runtime.h>
#include <math.h>
#include <float.h>
#include <stdint.h>

#define DEPTH  6
#define DIM    1024
#define HEADS  16
#define DH     64
#define INNER  2730
#define INNER_P 2732
#define INNER2 5460
#define BATCH  2
#define SEQ    1024
#define TOK    (BATCH*SEQ)
#define NBUCK  32
#define QKV_N  1152   // 1024 q + 64 k + 64 v

// ---------------- scratch ----------------
__device__ float g_x  [TOK*DIM];
__device__ float g_h  [TOK*DIM];
__device__ float g_qkv[(size_t)TOK*QKV_N + 32];
__device__ float g_o  [TOK*DIM];
__device__ float g_g1 [(size_t)TOK*INNER2 + 32];
__device__ float g_h3 [(size_t)TOK*INNER_P + 32];
__device__ float g_bias[SEQ*HEADS];
__device__ float g_wqkv[(size_t)DEPTH*DIM*QKV_N];

// ---------------- rel-pos bias ----------------
__global__ void bias_kernel(const float* __restrict__ rel_emb){
    int idx = blockIdx.x*blockDim.x + threadIdx.x;
    if (idx >= SEQ*HEADS) return;
    int delta = idx / HEADS;
    int h     = idx % HEADS;
    int bucket;
    if (delta < NBUCK/2) {
        bucket = delta;
    } else {
        float nf = (float)delta;
        int vl = (NBUCK/2) + (int)(logf(nf / (float)(NBUCK/2)) / logf(8.0f) * (float)(NBUCK/2));
        bucket = vl < (NBUCK-1) ? vl : (NBUCK-1);
    }
    g_bias[idx] = rel_emb[bucket*HEADS + h];
}

__global__ void scale_copy_kernel(const float* __restrict__ in, float* __restrict__ out, int n){
    int i = blockIdx.x*blockDim.x + threadIdx.x;
    if (i < n){ float v = in[i]; out[i] = v*0.1f + v*0.9f; }
}

// ---------------- pack wq|wkv into combined weight ----------------
__global__ void pack_qkv_kernel(const float* __restrict__ wq, const float* __restrict__ wkv,
                                float* __restrict__ wqkv){
    size_t i = (size_t)blockIdx.x*256 + threadIdx.x;
    if (i >= (size_t)DEPTH*DIM*QKV_N) return;
    int c = (int)(i % QKV_N);
    size_t rk = i / QKV_N;
    int k = (int)(rk % DIM);
    int l = (int)(rk / DIM);
    wqkv[i] = (c < DIM) ? wq[((size_t)l*DIM + k)*DIM + c]
                        : wkv[((size_t)l*DIM + k)*(2*DH) + (c - DIM)];
}

// ---------------- LayerNorm ----------------
__global__ __launch_bounds__(256) void ln_kernel(const float* __restrict__ in,
                                                 const float* __restrict__ g,
                                                 float* __restrict__ out, int D, int ldo){
    int t = blockIdx.x;
    const float* row = in + (size_t)t*D;
    float s = 0.f, s2 = 0.f;
    for (int i = threadIdx.x; i < D; i += blockDim.x){ float v = row[i]; s += v; s2 += v*v; }
    __shared__ float sh1[8], sh2[8];
    int lane = threadIdx.x & 31, warp = threadIdx.x >> 5;
    #pragma unroll
    for (int off = 16; off; off >>= 1){
        s  += __shfl_xor_sync(0xffffffffu, s,  off);
        s2 += __shfl_xor_sync(0xffffffffu, s2, off);
    }
    if (lane == 0){ sh1[warp] = s; sh2[warp] = s2; }
    __syncthreads();
    if (warp == 0){
        s  = (lane < 8) ? sh1[lane] : 0.f;
        s2 = (lane < 8) ? sh2[lane] : 0.f;
        #pragma unroll
        for (int off = 4; off; off >>= 1){
            s  += __shfl_xor_sync(0xffffffffu, s,  off);
            s2 += __shfl_xor_sync(0xffffffffu, s2, off);
        }
        if (lane == 0){ sh1[0] = s; sh2[0] = s2; }
    }
    __syncthreads();
    float m   = sh1[0] / (float)D;
    float var = sh2[0] / (float)D - m*m;
    float r   = rsqrtf(var + 1e-5f);
    for (int i = threadIdx.x; i < D; i += blockDim.x)
        out[(size_t)t*ldo + i] = (row[i] - m) * r * g[i];
    for (int i = D + threadIdx.x; i < ldo; i += blockDim.x)
        out[(size_t)t*ldo + i] = 0.f;
}

// ---------------- tf32 helpers ----------------
__device__ __forceinline__ float to_tf32(float x){
    uint32_t u; asm("cvt.rna.tf32.f32 %0, %1;" : "=r"(u) : "f"(x));
    return __uint_as_float(u);
}
__device__ __forceinline__ void mma_tf32(float* d, const uint32_t* a, const uint32_t* b){
    asm volatile(
        "mma.sync.aligned.m16n8k8.row.col.f32.tf32.tf32.f32 "
        "{%0,%1,%2,%3}, {%4,%5,%6,%7}, {%8,%9}, {%0,%1,%2,%3};\n"
        : "+f"(d[0]), "+f"(d[1]), "+f"(d[2]), "+f"(d[3])
        : "r"(a[0]), "r"(a[1]), "r"(a[2]), "r"(a[3]), "r"(b[0]), "r"(b[1]));
}

// ---------------- tf32 MMA GEMM: C[M,N] = A[M,K]@W[K,N] (+R) ----------------
// Block 128x128, KT=16, double-buffered; staging gathers whole fragment vectors
// so all shared stores are STS.128 (4 per thread per tile).
// A rows must be readable to k0+15 (+pads); B guarded per scalar.
__global__ __launch_bounds__(256, 2) void gemm_mma_kernel(const float* __restrict__ A,
                                                          const float* __restrict__ W,
                                                          const float* __restrict__ R,
                                                          float* __restrict__ C,
                                                          int M, int K, int N, int lda){
    // As: 512 fragment-vectors (float4): id = (g*8+mt)*32 + lane
    // Bs: 1024 fragment-pairs (float2): vid = (g*16+nt)*32 + lane
    __shared__ float As[2][2048];
    __shared__ float Bs[2][2048];

    const int bm = blockIdx.y * 128;
    const int bn = blockIdx.x * 128;
    const int t  = threadIdx.x;
    const int lane = t & 31;
    const int warp = t >> 5;
    const int wm = warp >> 2;          // 0..1
    const int wn = warp & 3;           // 0..3

    const int ntiles = (K + 15) / 16;
    float acc[4][4][4];
    #pragma unroll
    for (int i = 0; i < 4; i++)
        #pragma unroll
        for (int j = 0; j < 4; j++)
            #pragma unroll
            for (int q = 0; q < 4; q++) acc[i][j][q] = 0.f;

    float a_reg[2][4];
    float b_reg[8];

    // precomputed staging coordinates
    int a_row[2], a_col[2];
    #pragma unroll
    for (int v = 0; v < 2; v++){
        int id = 2*t + v;
        int al = id & 31, mt = (id >> 5) & 7, g = id >> 8;
        a_row[v] = bm + mt*16 + (al >> 2);
        a_col[v] = g*8 + (al & 3);
    }
    int b_col[4], b_k[4];
    #pragma unroll
    for (int u = 0; u < 4; u++){
        int vid = 4*t + u;
        int lb = vid & 31, nt = (vid >> 5) & 15, g = vid >> 9;
        b_col[u] = bn + nt*8 + (lb >> 2);
        b_k[u]   = g*8 + (lb & 3);
    }

    auto load_tile = [&](int k0){
        #pragma unroll
        for (int v = 0; v < 2; v++){
            const float* p = A + (size_t)a_row[v]*lda + k0 + a_col[v];
            a_reg[v][0] = p[0];
            a_reg[v][1] = p[(size_t)8*lda];
            a_reg[v][2] = p[4];
            a_reg[v][3] = p[(size_t)8*lda + 4];
        }
        #pragma unroll
        for (int u = 0; u < 4; u++){
            int kg = k0 + b_k[u];
            int cb = b_col[u];
            bool okc = (cb < N);
            b_reg[u*2+0] = (okc && kg     < K) ? W[(size_t)kg*N + cb]     : 0.f;
            b_reg[u*2+1] = (okc && kg + 4 < K) ? W[(size_t)(kg+4)*N + cb] : 0.f;
        }
    };
    auto store_tile = [&](int buf){
        #pragma unroll
        for (int v = 0; v < 2; v++){
            float4 q = make_float4(to_tf32(a_reg[v][0]), to_tf32(a_reg[v][1]),
                                   to_tf32(a_reg[v][2]), to_tf32(a_reg[v][3]));
            *reinterpret_cast<float4*>(&As[buf][(2*t + v)*4]) = q;
        }
        float4 q0 = make_float4(to_tf32(b_reg[0]), to_tf32(b_reg[1]),
                                to_tf32(b_reg[2]), to_tf32(b_reg[3]));
        float4 q1 = make_float4(to_tf32(b_reg[4]), to_tf32(b_reg[5]),
                                to_tf32(b_reg[6]), to_tf32(b_reg[7]));
        *reinterpret_cast<float4*>(&Bs[buf][8*t])     = q0;
        *reinterpret_cast<float4*>(&Bs[buf][8*t + 4]) = q1;
    };

    load_tile(0);
    store_tile(0);
    __syncthreads();

    int buf = 0;
    for (int tile = 0; tile < ntiles; tile++){
        const bool more = (tile + 1 < ntiles);
        if (more) load_tile((tile + 1) * 16);

        #pragma unroll
        for (int g = 0; g < 2; g++){
            uint32_t afr[4][4], bfr[4][2];
            #pragma unroll
            for (int i = 0; i < 4; i++)
                *reinterpret_cast<float4*>(afr[i]) =
                    *reinterpret_cast<const float4*>(&As[buf][((g*8 + wm*4 + i)*32 + lane)*4]);
            #pragma unroll
            for (int jn = 0; jn < 4; jn++)
                *reinterpret_cast<float2*>(bfr[jn]) =
                    *reinterpret_cast<const float2*>(&Bs[buf][((g*16 + wn*4 + jn)*32 + lane)*2]);
            #pragma unroll
            for (int i = 0; i < 4; i++)
                #pragma unroll
                for (int jn = 0; jn < 4; jn++)
                    mma_tf32(acc[i][jn], afr[i], bfr[jn]);
        }

        if (more) store_tile(buf ^ 1);
        __syncthreads();
        buf ^= 1;
    }

    // ---- epilogue ----
    const int r0 = bm + wm*64 + (lane >> 2);
    const int c0 = bn + wn*32 + (lane & 3)*2;
    #pragma unroll
    for (int i = 0; i < 4; i++){
        #pragma unroll
        for (int jn = 0; jn < 4; jn++){
            int col = c0 + jn*8;
            #pragma unroll
            for (int half = 0; half < 2; half++){
                int row = r0 + i*16 + half*8;
                size_t base = (size_t)row * N;
                float v0 = acc[i][jn][half*2 + 0];
                float v1 = acc[i][jn][half*2 + 1];
                if (col + 1 < N){
                    if (R){ v0 += R[base + col]; v1 += R[base + col + 1]; }
                    C[base + col]     = v0;
                    C[base + col + 1] = v1;
                } else if (col < N){
                    if (R) v0 += R[base + col];
                    C[base + col] = v0;
                }
            }
        }
    }
}

// ---------------- fused attention (reads fused qkv buffer) ----------------
#define AT_ROWS 16
#define ATTN_SMEM ((AT_ROWS*SEQ + AT_ROWS*DH + 2*64*65) * (int)sizeof(float))

__global__ __launch_bounds__(256) void attn_kernel(const float* __restrict__ qkv,
                                                   float* __restrict__ o){
    extern __shared__ float sm[];
    float* S  = sm;
    float* Qs = S  + AT_ROWS*SEQ;
    float* Ks = Qs + AT_ROWS*DH;
    float* Vs = Ks + 64*65;
    int it = blockIdx.x;
    int h  = blockIdx.y;
    int b  = blockIdx.z;
    int i0 = it * AT_ROWS;
    int tid = threadIdx.x;

    for (int idx = tid; idx < AT_ROWS*DH; idx += 256){
        int r = idx / DH, d = idx % DH;
        Qs[r*DH + d] = qkv[(size_t)(b*SEQ + i0 + r)*QKV_N + h*DH + d] * 0.125f;
    }
    __syncthreads();

    int jmax = i0 + AT_ROWS - 1;
    int njt  = jmax/64 + 1;
    int jj = tid & 63;
    int rg = tid >> 6;

    for (int jt = 0; jt < njt; jt++){
        for (int idx = tid; idx < 64*DH; idx += 256){
            int kr = idx / DH, d = idx % DH;
            Ks[kr*65 + d] = qkv[(size_t)(b*SEQ + jt*64 + kr)*QKV_N + DIM + d];
        }
        __syncthreads();
        int j = jt*64 + jj;
        #pragma unroll
        for (int ri = 0; ri < 4; ri++){
            int r = rg*4 + ri;
            float acc = 0.f;
            #pragma unroll
            for (int d = 0; d < DH; d++) acc += Qs[r*DH + d] * Ks[jj*65 + d];
            int i = i0 + r;
            S[r*SEQ + j] = (j <= i) ? (acc + g_bias[(i-j)*HEADS + h]) : -FLT_MAX;
        }
        __syncthreads();
    }

    int warp = tid >> 5, lane = tid & 31;
    int ncol = njt * 64;
    for (int r = warp*2; r < warp*2 + 2; r++){
        int i = i0 + r;
        float mx = -FLT_MAX;
        for (int j = lane; j <= i; j += 32) mx = fmaxf(mx, S[r*SEQ + j]);
        #pragma unroll
        for (int off = 16; off; off >>= 1) mx = fmaxf(mx, __shfl_xor_sync(0xffffffffu, mx, off));
        float sum = 0.f;
        for (int j = lane; j <= i; j += 32) sum += expf(S[r*SEQ + j] - mx);
        #pragma unroll
        for (int off = 16; off; off >>= 1) sum += __shfl_xor_sync(0xffffffffu, sum, off);
        float inv = 1.f / sum;
        for (int j = lane; j < ncol; j += 32){
            float p = (j <= i) ? expf(S[r*SEQ + j] - mx) * inv : 0.f;
            S[r*SEQ + j] = p;
        }
    }
    __syncthreads();

    int d = tid & 63;
    float accv[4] = {0.f, 0.f, 0.f, 0.f};
    for (int jt = 0; jt < njt; jt++){
        for (int idx = tid; idx < 64*DH; idx += 256){
            int vr = idx / DH, dd = idx % DH;
            Vs[vr*65 + dd] = qkv[(size_t)(b*SEQ + jt*64 + vr)*QKV_N + DIM + DH + dd];
        }
        __syncthreads();
        #pragma unroll
        for (int ri = 0; ri < 4; ri++){
            int r = rg*4 + ri;
            float a = 0.f;
            #pragma unroll 8
            for (int jl = 0; jl < 64; jl++) a += S[r*SEQ + jt*64 + jl] * Vs[jl*65 + d];
            accv[ri] += a;
        }
        __syncthreads();
    }
    #pragma unroll
    for (int ri = 0; ri < 4; ri++){
        int r = rg*4 + ri;
        o[(size_t)(b*SEQ + i0 + r)*DIM + h*DH + d] = accv[ri];
    }
}

// ---------------- fused causal conv(3) + GELU-GLU + LayerNorm ----------------
__global__ __launch_bounds__(256) void convglu_ln_kernel(const float* __restrict__ g1,
                                                         const float* __restrict__ cw,
                                                         const float* __restrict__ lng,
                                                         float* __restrict__ out){
    __shared__ float hbuf[INNER];
    __shared__ float sh1[8], sh2[8];
    int t = blockIdx.x;
    int n = t & (SEQ-1);
    size_t base = (size_t)t * INNER2;
    float s = 0.f, s2 = 0.f;
    for (int c = threadIdx.x; c < INNER; c += blockDim.x){
        float w0 = cw[c*3+0], w1 = cw[c*3+1], w2 = cw[c*3+2];
        float a = ((n >= 2) ? g1[base - 2*(size_t)INNER2 + c] : 0.f) * w0
                + ((n >= 1) ? g1[base -   (size_t)INNER2 + c] : 0.f) * w1
                +              g1[base + c] * w2;
        int cg = c + INNER;
        float v0 = cw[cg*3+0], v1 = cw[cg*3+1], v2 = cw[cg*3+2];
        float g = ((n >= 2) ? g1[base - 2*(size_t)INNER2 + cg] : 0.f) * v0
                + ((n >= 1) ? g1[base -   (size_t)INNER2 + cg] : 0.f) * v1
                +              g1[base + cg] * v2;
        float gg = 0.5f * g * (1.f + erff(g * 0.70710678118654752f));
        float h = gg * a;
        hbuf[c] = h;
        s += h; s2 += h*h;
    }
    int lane = threadIdx.x & 31, warp = threadIdx.x >> 5;
    #pragma unroll
    for (int off = 16; off; off >>= 1){
        s  += __shfl_xor_sync(0xffffffffu, s,  off);
        s2 += __shfl_xor_sync(0xffffffffu, s2, off);
    }
    if (lane == 0){ sh1[warp] = s; sh2[warp] = s2; }
    __syncthreads();
    if (warp == 0){
        s  = (lane < 8) ? sh1[lane] : 0.f;
        s2 = (lane < 8) ? sh2[lane] : 0.f;
        #pragma unroll
        for (int off = 4; off; off >>= 1){
            s  += __shfl_xor_sync(0xffffffffu, s,  off);
            s2 += __shfl_xor_sync(0xffffffffu, s2, off);
        }
        if (lane == 0){ sh1[0] = s; sh2[0] = s2; }
    }
    __syncthreads();
    float m   = sh1[0] / (float)INNER;
    float var = sh2[0] / (float)INNER - m*m;
    float r   = rsqrtf(var + 1e-5f);
    for (int c = threadIdx.x; c < INNER; c += blockDim.x)
        out[(size_t)t*INNER_P + c] = (hbuf[c] - m) * r * lng[c];
    for (int c = INNER + threadIdx.x; c < INNER_P; c += blockDim.x)
        out[(size_t)t*INNER_P + c] = 0.f;
}

// ---------------- launch helpers ----------------
static inline void run_gemm(const float* A, const float* W, const float* R, float* C,
                            int M, int K, int N, int lda){
    dim3 grid((N + 127)/128, M/128);
    gemm_mma_kernel<<<grid, 256>>>(A, W, R, C, M, K, N, lda);
}

extern "C" void kernel_launch(void* const* d_in, const int* in_sizes, int n_in,
                              void* d_out, int out_size){
    const float* x     = (const float*)d_in[0];
    const float* rel   = (const float*)d_in[1];
    const float* qn_g  = (const float*)d_in[2];
    const float* wq    = (const float*)d_in[3];
    const float* wkv   = (const float*)d_in[4];
    const float* wo    = (const float*)d_in[5];
    const float* ln1g  = (const float*)d_in[6];
    const float* w1    = (const float*)d_in[7];
    const float* convw = (const float*)d_in[8];
    const float* ln2g  = (const float*)d_in[9];
    const float* w2    = (const float*)d_in[10];
    const float* fing  = (const float*)d_in[11];
    float* out = (float*)d_out;

    float *px, *ph, *pqkv, *po, *pg1, *ph3, *pwqkv;
    cudaGetSymbolAddress((void**)&px,    g_x);
    cudaGetSymbolAddress((void**)&ph,    g_h);
    cudaGetSymbolAddress((void**)&pqkv,  g_qkv);
    cudaGetSymbolAddress((void**)&po,    g_o);
    cudaGetSymbolAddress((void**)&pg1,   g_g1);
    cudaGetSymbolAddress((void**)&ph3,   g_h3);
    cudaGetSymbolAddress((void**)&pwqkv, g_wqkv);

    cudaFuncSetAttribute(attn_kernel, cudaFuncAttributeMaxDynamicSharedMemorySize, ATTN_SMEM);

    bias_kernel<<<(SEQ*HEADS + 255)/256, 256>>>(rel);
    scale_copy_kernel<<<(TOK*DIM + 255)/256, 256>>>(x, px, TOK*DIM);
    {
        size_t tot = (size_t)DEPTH*DIM*QKV_N;
        pack_qkv_kernel<<<(unsigned)((tot + 255)/256), 256>>>(wq, wkv, pwqkv);
    }

    for (int l = 0; l < DEPTH; l++){
        // attention block
        ln_kernel<<<TOK, 256>>>(px, qn_g + l*DIM, ph, DIM, DIM);
        run_gemm(ph, pwqkv + (size_t)l*DIM*QKV_N, nullptr, pqkv, TOK, DIM, QKV_N, DIM);
        dim3 agrid(SEQ/AT_ROWS, HEADS, BATCH);
        attn_kernel<<<agrid, 256, ATTN_SMEM>>>(pqkv, po);
        run_gemm(po, wo + (size_t)l*DIM*DIM, px, px, TOK, DIM, DIM, DIM);

        // conv-GLU MLP block
        ln_kernel<<<TOK, 256>>>(px, ln1g + l*DIM, ph, DIM, DIM);
        run_gemm(ph, w1 + (size_t)l*DIM*INNER2, nullptr, pg1, TOK, DIM, INNER2, DIM);
        convglu_ln_kernel<<<TOK, 256>>>(pg1, convw + (size_t)l*INNER2*3,
                                        ln2g + (size_t)l*INNER, ph3);
        run_gemm(ph3, w2 + (size_t)l*INNER*DIM, px, px, TOK, INNER, DIM, INNER_P);
    }
    ln_kernel<<<TOK, 256>>>(px, fing, out, DIM, DIM);
}